// round 1
// baseline (speedup 1.0000x reference)
#include <cuda_runtime.h>
#include <cstddef>

#define NUM_FIELDS 16
#define FIELD_DIM  31250
#define VOCAB      500000
#define NUM_PAIRS  120
#define EMBED      32
#define BATCH_TPB  960   // 120 pairs * 8 float4-lanes

// Packed (i,j) pair table for triu(16, k=1): entry = i | (j<<8).
#define P(i,j) ((i) | ((j) << 8))
__constant__ int c_pair[NUM_PAIRS] = {
    P(0,1),P(0,2),P(0,3),P(0,4),P(0,5),P(0,6),P(0,7),P(0,8),P(0,9),P(0,10),P(0,11),P(0,12),P(0,13),P(0,14),P(0,15),
    P(1,2),P(1,3),P(1,4),P(1,5),P(1,6),P(1,7),P(1,8),P(1,9),P(1,10),P(1,11),P(1,12),P(1,13),P(1,14),P(1,15),
    P(2,3),P(2,4),P(2,5),P(2,6),P(2,7),P(2,8),P(2,9),P(2,10),P(2,11),P(2,12),P(2,13),P(2,14),P(2,15),
    P(3,4),P(3,5),P(3,6),P(3,7),P(3,8),P(3,9),P(3,10),P(3,11),P(3,12),P(3,13),P(3,14),P(3,15),
    P(4,5),P(4,6),P(4,7),P(4,8),P(4,9),P(4,10),P(4,11),P(4,12),P(4,13),P(4,14),P(4,15),
    P(5,6),P(5,7),P(5,8),P(5,9),P(5,10),P(5,11),P(5,12),P(5,13),P(5,14),P(5,15),
    P(6,7),P(6,8),P(6,9),P(6,10),P(6,11),P(6,12),P(6,13),P(6,14),P(6,15),
    P(7,8),P(7,9),P(7,10),P(7,11),P(7,12),P(7,13),P(7,14),P(7,15),
    P(8,9),P(8,10),P(8,11),P(8,12),P(8,13),P(8,14),P(8,15),
    P(9,10),P(9,11),P(9,12),P(9,13),P(9,14),P(9,15),
    P(10,11),P(10,12),P(10,13),P(10,14),P(10,15),
    P(11,12),P(11,13),P(11,14),P(11,15),
    P(12,13),P(12,14),P(12,15),
    P(13,14),P(13,15),
    P(14,15)
};
#undef P

// One block per batch row. 960 threads: thread t -> pair p = t>>3, float4-lane q = t&7.
// out[b, p, 4q:4q+4] = W[j, idx_i, 4q:4q+4] * W[i, idx_j, 4q:4q+4]
__global__ __launch_bounds__(BATCH_TPB)
void ffm_pair_kernel(const int* __restrict__ x,
                     const float4* __restrict__ W,   // (16, 500000, 8) float4
                     float4* __restrict__ out)       // (B, 120, 8) float4
{
    __shared__ int s_idx[NUM_FIELDS];

    const int b = blockIdx.x;
    const int t = threadIdx.x;

    if (t < NUM_FIELDS) {
        // idx = x + field offset (offsets are f * 31250)
        s_idx[t] = x[b * NUM_FIELDS + t] + t * FIELD_DIM;
    }
    __syncthreads();

    const int p  = t >> 3;
    const int q  = t & 7;
    const int ij = c_pair[p];
    const int i  = ij & 0xff;
    const int j  = ij >> 8;

    const int idx_i = s_idx[i];
    const int idx_j = s_idx[j];

    // W row stride = 8 float4 (32 floats)
    const float4 a  = __ldg(&W[((size_t)j * VOCAB + idx_i) * 8 + q]);
    const float4 bb = __ldg(&W[((size_t)i * VOCAB + idx_j) * 8 + q]);

    float4 r;
    r.x = a.x * bb.x;
    r.y = a.y * bb.y;
    r.z = a.z * bb.z;
    r.w = a.w * bb.w;

    // float4 index: b*960 + p*8 + q == b*960 + t  (fully coalesced per block)
    out[(size_t)b * BATCH_TPB + t] = r;
}

extern "C" void kernel_launch(void* const* d_in, const int* in_sizes, int n_in,
                              void* d_out, int out_size)
{
    // Inputs: x int32 (16384*16 = 262144 elems), W float32 (16*500000*32 = 256M elems).
    // Pick defensively by element count.
    const int* x = nullptr;
    const float* W = nullptr;
    if (n_in >= 2) {
        if (in_sizes[0] < in_sizes[1]) {
            x = (const int*)d_in[0];
            W = (const float*)d_in[1];
        } else {
            x = (const int*)d_in[1];
            W = (const float*)d_in[0];
        }
    }

    const int batch = (x && W) ? (in_sizes[0] < in_sizes[1] ? in_sizes[0] : in_sizes[1]) / NUM_FIELDS : 0;

    ffm_pair_kernel<<<batch, BATCH_TPB>>>(x, (const float4*)W, (float4*)d_out);
}

// round 2
// speedup vs baseline: 1.4241x; 1.4241x over previous
#include <cuda_runtime.h>
#include <cstddef>

#define NUM_FIELDS 16
#define FIELD_DIM  31250
#define VOCAB      500000
#define NUM_PAIRS  120
#define ROWS_PER_BLOCK 128
#define TPB 512            // 64 rows * 8 float4-lanes, 2 rows per thread

// Packed (i,j) pair table for triu(16, k=1): entry = i | (j<<8).
#define P(i,j) ((i) | ((j) << 8))
__constant__ int c_pair[NUM_PAIRS] = {
    P(0,1),P(0,2),P(0,3),P(0,4),P(0,5),P(0,6),P(0,7),P(0,8),P(0,9),P(0,10),P(0,11),P(0,12),P(0,13),P(0,14),P(0,15),
    P(1,2),P(1,3),P(1,4),P(1,5),P(1,6),P(1,7),P(1,8),P(1,9),P(1,10),P(1,11),P(1,12),P(1,13),P(1,14),P(1,15),
    P(2,3),P(2,4),P(2,5),P(2,6),P(2,7),P(2,8),P(2,9),P(2,10),P(2,11),P(2,12),P(2,13),P(2,14),P(2,15),
    P(3,4),P(3,5),P(3,6),P(3,7),P(3,8),P(3,9),P(3,10),P(3,11),P(3,12),P(3,13),P(3,14),P(3,15),
    P(4,5),P(4,6),P(4,7),P(4,8),P(4,9),P(4,10),P(4,11),P(4,12),P(4,13),P(4,14),P(4,15),
    P(5,6),P(5,7),P(5,8),P(5,9),P(5,10),P(5,11),P(5,12),P(5,13),P(5,14),P(5,15),
    P(6,7),P(6,8),P(6,9),P(6,10),P(6,11),P(6,12),P(6,13),P(6,14),P(6,15),
    P(7,8),P(7,9),P(7,10),P(7,11),P(7,12),P(7,13),P(7,14),P(7,15),
    P(8,9),P(8,10),P(8,11),P(8,12),P(8,13),P(8,14),P(8,15),
    P(9,10),P(9,11),P(9,12),P(9,13),P(9,14),P(9,15),
    P(10,11),P(10,12),P(10,13),P(10,14),P(10,15),
    P(11,12),P(11,13),P(11,14),P(11,15),
    P(12,13),P(12,14),P(12,15),
    P(13,14),P(13,15),
    P(14,15)
};
#undef P

// Pair-major schedule: blockIdx.y = pair (contiguous block-id span per pair ->
// the pair's two 4MB index windows stay L2-resident for all 16384 accesses),
// blockIdx.x = batch tile of 128 rows. Each thread: 2 rows x 1 float4 lane.
__global__ __launch_bounds__(TPB)
void ffm_pairmajor_kernel(const int* __restrict__ x,
                          const float4* __restrict__ W,   // (16, 500000, 8) float4
                          float4* __restrict__ out,       // (B, 120, 8) float4
                          int batch)
{
    const int p    = blockIdx.y;
    const int t    = threadIdx.x;
    const int r    = t >> 3;            // 0..63
    const int q    = t & 7;             // float4 lane within embedding
    const int row0 = blockIdx.x * ROWS_PER_BLOCK + r;
    const int row1 = row0 + 64;

    const int ij = c_pair[p];
    const int i  = ij & 0xff;
    const int j  = ij >> 8;

    // Index loads (x is 1MB, fully L2-resident; same addr across the 8 lanes
    // of a row -> single transaction + broadcast).
    const int ii0 = __ldg(&x[row0 * NUM_FIELDS + i]) + i * FIELD_DIM;
    const int jj0 = __ldg(&x[row0 * NUM_FIELDS + j]) + j * FIELD_DIM;
    const int ii1 = __ldg(&x[row1 * NUM_FIELDS + i]) + i * FIELD_DIM;
    const int jj1 = __ldg(&x[row1 * NUM_FIELDS + j]) + j * FIELD_DIM;

    // 4 independent 128B gathers in flight per thread (MLP=4).
    const float4 a0 = __ldg(&W[((size_t)j * VOCAB + ii0) * 8 + q]);
    const float4 b0 = __ldg(&W[((size_t)i * VOCAB + jj0) * 8 + q]);
    const float4 a1 = __ldg(&W[((size_t)j * VOCAB + ii1) * 8 + q]);
    const float4 b1 = __ldg(&W[((size_t)i * VOCAB + jj1) * 8 + q]);

    float4 r0, r1;
    r0.x = a0.x * b0.x;  r0.y = a0.y * b0.y;  r0.z = a0.z * b0.z;  r0.w = a0.w * b0.w;
    r1.x = a1.x * b1.x;  r1.y = a1.y * b1.y;  r1.z = a1.z * b1.z;  r1.w = a1.w * b1.w;

    // out float4 layout: (row, pair, 8). 8 lanes -> one contiguous 128B line.
    const size_t o0 = (size_t)row0 * (NUM_PAIRS * 8) + p * 8 + q;
    const size_t o1 = (size_t)row1 * (NUM_PAIRS * 8) + p * 8 + q;
    out[o0] = r0;
    out[o1] = r1;
}

extern "C" void kernel_launch(void* const* d_in, const int* in_sizes, int n_in,
                              void* d_out, int out_size)
{
    // Inputs: x int32 (16384*16 elems), W float32 (16*500000*32 elems).
    const int* x = nullptr;
    const float* W = nullptr;
    int x_elems = 0;
    if (n_in >= 2) {
        if (in_sizes[0] < in_sizes[1]) {
            x = (const int*)d_in[0];
            W = (const float*)d_in[1];
            x_elems = in_sizes[0];
        } else {
            x = (const int*)d_in[1];
            W = (const float*)d_in[0];
            x_elems = in_sizes[1];
        }
    }

    const int batch = x_elems / NUM_FIELDS;
    const int tiles = batch / ROWS_PER_BLOCK;   // 16384/128 = 128

    dim3 grid(tiles, NUM_PAIRS);
    ffm_pairmajor_kernel<<<grid, TPB>>>(x, (const float4*)W, (float4*)d_out, batch);
}

// round 4
// speedup vs baseline: 1.4259x; 1.0013x over previous
#include <cuda_runtime.h>
#include <cstddef>
#include <cstdint>

#define NUM_FIELDS 16
#define FIELD_DIM  31250
#define VOCAB      500000
#define NUM_PAIRS  120
#define ROWS_PER_BLOCK 128
#define TPB 512            // 128 rows * 4 lanes (32B per lane), 1 row per thread

// Packed (i,j) pair table for triu(16, k=1): entry = i | (j<<8).
#define P(i,j) ((i) | ((j) << 8))
__constant__ int c_pair[NUM_PAIRS] = {
    P(0,1),P(0,2),P(0,3),P(0,4),P(0,5),P(0,6),P(0,7),P(0,8),P(0,9),P(0,10),P(0,11),P(0,12),P(0,13),P(0,14),P(0,15),
    P(1,2),P(1,3),P(1,4),P(1,5),P(1,6),P(1,7),P(1,8),P(1,9),P(1,10),P(1,11),P(1,12),P(1,13),P(1,14),P(1,15),
    P(2,3),P(2,4),P(2,5),P(2,6),P(2,7),P(2,8),P(2,9),P(2,10),P(2,11),P(2,12),P(2,13),P(2,14),P(2,15),
    P(3,4),P(3,5),P(3,6),P(3,7),P(3,8),P(3,9),P(3,10),P(3,11),P(3,12),P(3,13),P(3,14),P(3,15),
    P(4,5),P(4,6),P(4,7),P(4,8),P(4,9),P(4,10),P(4,11),P(4,12),P(4,13),P(4,14),P(4,15),
    P(5,6),P(5,7),P(5,8),P(5,9),P(5,10),P(5,11),P(5,12),P(5,13),P(5,14),P(5,15),
    P(6,7),P(6,8),P(6,9),P(6,10),P(6,11),P(6,12),P(6,13),P(6,14),P(6,15),
    P(7,8),P(7,9),P(7,10),P(7,11),P(7,12),P(7,13),P(7,14),P(7,15),
    P(8,9),P(8,10),P(8,11),P(8,12),P(8,13),P(8,14),P(8,15),
    P(9,10),P(9,11),P(9,12),P(9,13),P(9,14),P(9,15),
    P(10,11),P(10,12),P(10,13),P(10,14),P(10,15),
    P(11,12),P(11,13),P(11,14),P(11,15),
    P(12,13),P(12,14),P(12,15),
    P(13,14),P(13,15),
    P(14,15)
};
#undef P

// 256-bit (32B) gather with L2 evict-last — the only ld width ptxas accepts
// the evict_last modifier on for sm_103. Protects the pair's hot 4MB index
// windows in L2 against store/stream pressure.
__device__ __forceinline__ void ldg_el8(const float* p, uint32_t v[8]) {
    asm volatile("ld.global.nc.L2::evict_last.v8.b32 {%0,%1,%2,%3,%4,%5,%6,%7}, [%8];"
                 : "=r"(v[0]), "=r"(v[1]), "=r"(v[2]), "=r"(v[3]),
                   "=r"(v[4]), "=r"(v[5]), "=r"(v[6]), "=r"(v[7])
                 : "l"(p));
}

// Streaming store, evict-first: output is never re-read; don't pollute L2.
__device__ __forceinline__ void stg_cs(float* p, float x, float y, float z, float w) {
    asm volatile("st.global.cs.v4.f32 [%0], {%1,%2,%3,%4};"
                 :: "l"(p), "f"(x), "f"(y), "f"(z), "f"(w)
                 : "memory");
}

// Pair-major schedule: blockIdx.y = pair (contiguous block-id span per pair ->
// the pair's two 4MB index windows stay L2-resident for all 16384 accesses),
// blockIdx.x = batch tile of 128 rows. Each thread: 1 row x 32B lane.
__global__ __launch_bounds__(TPB, 4)
void ffm_pairmajor_kernel(const int* __restrict__ x,
                          const float* __restrict__ W,    // (16, 500000, 32) float
                          float* __restrict__ out,        // (B, 120, 32) float
                          int batch)
{
    const int p   = blockIdx.y;
    const int t   = threadIdx.x;
    const int q   = t & 3;              // 32B chunk within the 128B embedding
    const int r   = t >> 2;             // 0..127
    const int row = blockIdx.x * ROWS_PER_BLOCK + r;

    const int ij = c_pair[p];
    const int i  = ij & 0xff;
    const int j  = ij >> 8;

    // Index loads (x is 1MB, L2-resident; same addr across the 4 lanes of a
    // row -> broadcast).
    const int ii = __ldg(&x[row * NUM_FIELDS + i]) + i * FIELD_DIM;
    const int jj = __ldg(&x[row * NUM_FIELDS + j]) + j * FIELD_DIM;

    // Two independent 256-bit gathers in flight per thread.
    uint32_t a[8], b[8];
    ldg_el8(W + ((size_t)j * VOCAB + ii) * 32 + q * 8, a);
    ldg_el8(W + ((size_t)i * VOCAB + jj) * 32 + q * 8, b);

    float r0 = __uint_as_float(a[0]) * __uint_as_float(b[0]);
    float r1 = __uint_as_float(a[1]) * __uint_as_float(b[1]);
    float r2 = __uint_as_float(a[2]) * __uint_as_float(b[2]);
    float r3 = __uint_as_float(a[3]) * __uint_as_float(b[3]);
    float r4 = __uint_as_float(a[4]) * __uint_as_float(b[4]);
    float r5 = __uint_as_float(a[5]) * __uint_as_float(b[5]);
    float r6 = __uint_as_float(a[6]) * __uint_as_float(b[6]);
    float r7 = __uint_as_float(a[7]) * __uint_as_float(b[7]);

    // out float layout: (row, pair, 32); 4 lanes cover one contiguous 128B line.
    float* o = out + (size_t)row * (NUM_PAIRS * 32) + p * 32 + q * 8;
    stg_cs(o,     r0, r1, r2, r3);
    stg_cs(o + 4, r4, r5, r6, r7);
}

extern "C" void kernel_launch(void* const* d_in, const int* in_sizes, int n_in,
                              void* d_out, int out_size)
{
    // Inputs: x int32 (16384*16 elems), W float32 (16*500000*32 elems).
    const int* x = nullptr;
    const float* W = nullptr;
    int x_elems = 0;
    if (n_in >= 2) {
        if (in_sizes[0] < in_sizes[1]) {
            x = (const int*)d_in[0];
            W = (const float*)d_in[1];
            x_elems = in_sizes[0];
        } else {
            x = (const int*)d_in[1];
            W = (const float*)d_in[0];
            x_elems = in_sizes[1];
        }
    }

    const int batch = x_elems / NUM_FIELDS;
    const int tiles = batch / ROWS_PER_BLOCK;   // 16384/128 = 128

    dim3 grid(tiles, NUM_PAIRS);
    ffm_pairmajor_kernel<<<grid, TPB>>>(x, W, (float*)d_out, batch);
}